// round 2
// baseline (speedup 1.0000x reference)
#include <cuda_runtime.h>
#include <math.h>
#include <stdint.h>

typedef unsigned long long u64;
typedef unsigned int u32;

#define P_PROP 1024
#define NCLS   80
#define NDET   (P_PROP * NCLS)   // 81920
#define KNMS   2048
#define FEAT   12544             // 256*7*7
#define CLIN   1024
#define BBOX_CLIP 4.135166556742356f

// ------------------------- scratch (device globals; no runtime alloc) ------
__device__ float  g_x   [P_PROP * FEAT];     // roi features (P,12544)
__device__ float  g_h1  [P_PROP * CLIN];
__device__ float  g_h2  [P_PROP * CLIN];
__device__ float  g_cls [P_PROP * 81];
__device__ float  g_reg [P_PROP * 320];
__device__ float  g_scr [P_PROP * NCLS];
__device__ float4 g_boxes[NDET];
__device__ u64    g_keysA[NDET];
__device__ u64    g_keysB[NDET / 2 + 4096];
__device__ float4 g_bk  [KNMS];
__device__ float4 g_ob  [KNMS];
__device__ float  g_sk  [KNMS];
__device__ int    g_ck  [KNMS];
__device__ int    g_imk [KNMS];
__device__ unsigned char g_vk  [KNMS];
__device__ unsigned char g_keep[KNMS];
__device__ u64    g_mask[KNMS * 32];

// --------------------------------- RoIAlign --------------------------------
// grid = P_PROP*7 blocks, 256 threads. block -> (proposal p, output row oy).
// Warp lanes 0..27 = the 28 x-tap columns (2 taps * 14 x-samples);
// warps stride over 256 channels (32 channels/warp).
__global__ __launch_bounds__(256) void roi_align_kernel(
    const float* __restrict__ props, const int* __restrict__ imidx,
    const float* __restrict__ f0, const float* __restrict__ f1,
    const float* __restrict__ f2, const float* __restrict__ f3)
{
    const int p  = blockIdx.x / 7;
    const int oy = blockIdx.x % 7;

    __shared__ int   s_xc[28];
    __shared__ float s_xw[28];
    __shared__ int   s_yr[4];
    __shared__ float s_yw[4];
    __shared__ int   s_l, s_im, s_H, s_W;

    if (threadIdx.x < 32) {
        float4 pr = ((const float4*)props)[p];
        float w = pr.z - pr.x, h = pr.w - pr.y;
        float t = sqrtf(w * h) / 224.0f + 1e-8f;
        float lv = floorf(4.0f + log2f(t));
        int l = (int)fminf(fmaxf(lv, 2.0f), 5.0f) - 2;
        int H = 160 >> l, W = 160 >> l;
        float inv = 1.0f / (float)(4 << l);
        float x1 = pr.x * inv - 0.5f, x2 = pr.z * inv - 0.5f;
        float y1 = pr.y * inv - 0.5f, y2 = pr.w * inv - 0.5f;
        float bw = (x2 - x1) / 7.0f, bh = (y2 - y1) / 7.0f;
        int lane = threadIdx.x;
        if (lane < 28) {                       // lane = 2*j + tap
            int j = lane >> 1;
            float g  = ((float)j + 0.5f) * 0.5f;
            float xs = x1 + bw * g;
            float vx = (xs > -1.0f && xs < (float)W) ? 1.0f : 0.0f;
            float v  = fminf(fmaxf(xs, 0.0f), (float)W - 1.0f);
            float lo = floorf(v);
            int loi = (int)lo;
            int hii = min(loi + 1, W - 1);
            float fx = v - lo;
            s_xc[lane] = (lane & 1) ? hii : loi;
            s_xw[lane] = (lane & 1) ? (fx * vx) : ((1.0f - fx) * vx);
        }
        if (lane < 4) {                        // lane = 2*q + tap
            int q = lane >> 1;
            int sy = oy * 2 + q;
            float g  = ((float)sy + 0.5f) * 0.5f;
            float ys = y1 + bh * g;
            float vy = (ys > -1.0f && ys < (float)H) ? 1.0f : 0.0f;
            float v  = fminf(fmaxf(ys, 0.0f), (float)H - 1.0f);
            float lo = floorf(v);
            int loi = (int)lo;
            int hii = min(loi + 1, H - 1);
            float fy = v - lo;
            s_yr[lane] = (lane & 1) ? hii : loi;
            s_yw[lane] = (lane & 1) ? (fy * vy) : ((1.0f - fy) * vy);
        }
        if (lane == 0) { s_l = l; s_im = imidx[p]; s_H = H; s_W = W; }
    }
    __syncthreads();

    const int l = s_l, H = s_H, W = s_W, im = s_im;
    const float* fm = (l == 0) ? f0 : (l == 1) ? f1 : (l == 2) ? f2 : f3;
    const float* base_im = fm + (size_t)im * 256 * H * W;

    const int warp = threadIdx.x >> 5;
    const int lane = threadIdx.x & 31;
    const float xw = (lane < 28) ? s_xw[lane] : 0.0f;
    const int   xc = (lane < 28) ? s_xc[lane] : 0;
    const int r0 = s_yr[0], r1 = s_yr[1], r2 = s_yr[2], r3 = s_yr[3];
    const float w0 = s_yw[0], w1 = s_yw[1], w2 = s_yw[2], w3 = s_yw[3];

    for (int c = warp; c < 256; c += 8) {
        const float* bc = base_im + (size_t)c * H * W;
        float acc = w0 * bc[r0 * W + xc]
                  + w1 * bc[r1 * W + xc]
                  + w2 * bc[r2 * W + xc]
                  + w3 * bc[r3 * W + xc];
        float m = acc * xw;
        m += __shfl_xor_sync(0xffffffffu, m, 1);
        m += __shfl_xor_sync(0xffffffffu, m, 2);
        if (lane < 28 && (lane & 3) == 0)
            g_x[(size_t)p * FEAT + c * 49 + oy * 7 + (lane >> 2)] = m * 0.25f;
    }
}

// ---------------------------------- GEMM -----------------------------------
// C[m][n] = act( sum_k A[m][k]*B[n][k] + bias[n] ), A: M x K, B: N x K (row-major)
// 64x64 tile, BK=16, 256 threads, 4x4 per thread.
__global__ __launch_bounds__(256) void gemm_kernel(
    const float* __restrict__ A, const float* __restrict__ B,
    const float* __restrict__ bias, float* __restrict__ C,
    int N, int K, int relu)
{
    __shared__ float As[16][68];
    __shared__ float Bs[16][68];
    const int bm = blockIdx.y * 64;
    const int bn = blockIdx.x * 64;
    const int tid = threadIdx.x;
    const int lr = tid >> 2;            // 0..63
    const int lc = (tid & 3) << 2;      // 0,4,8,12
    const int ty = tid >> 4;            // 0..15
    const int tx = tid & 15;

    float acc[4][4];
    #pragma unroll
    for (int i = 0; i < 4; i++)
        #pragma unroll
        for (int j = 0; j < 4; j++) acc[i][j] = 0.0f;

    const float* Aptr = A + (size_t)(bm + lr) * K;
    const bool bvalid = (bn + lr) < N;
    const float* Bptr = bvalid ? (B + (size_t)(bn + lr) * K) : B;

    for (int k0 = 0; k0 < K; k0 += 16) {
        float4 av = *(const float4*)(Aptr + k0 + lc);
        float4 bv = make_float4(0.f, 0.f, 0.f, 0.f);
        if (bvalid) bv = *(const float4*)(Bptr + k0 + lc);
        As[lc+0][lr] = av.x; As[lc+1][lr] = av.y; As[lc+2][lr] = av.z; As[lc+3][lr] = av.w;
        Bs[lc+0][lr] = bv.x; Bs[lc+1][lr] = bv.y; Bs[lc+2][lr] = bv.z; Bs[lc+3][lr] = bv.w;
        __syncthreads();
        #pragma unroll
        for (int kk = 0; kk < 16; kk++) {
            float4 a = *(const float4*)(&As[kk][ty << 2]);
            float4 b = *(const float4*)(&Bs[kk][tx << 2]);
            acc[0][0] += a.x * b.x; acc[0][1] += a.x * b.y; acc[0][2] += a.x * b.z; acc[0][3] += a.x * b.w;
            acc[1][0] += a.y * b.x; acc[1][1] += a.y * b.y; acc[1][2] += a.y * b.z; acc[1][3] += a.y * b.w;
            acc[2][0] += a.z * b.x; acc[2][1] += a.z * b.y; acc[2][2] += a.z * b.z; acc[2][3] += a.z * b.w;
            acc[3][0] += a.w * b.x; acc[3][1] += a.w * b.y; acc[3][2] += a.w * b.z; acc[3][3] += a.w * b.w;
        }
        __syncthreads();
    }

    #pragma unroll
    for (int i = 0; i < 4; i++) {
        int m = bm + (ty << 2) + i;
        #pragma unroll
        for (int j = 0; j < 4; j++) {
            int n = bn + (tx << 2) + j;
            if (n < N) {
                float v = acc[i][j] + bias[n];
                if (relu) v = fmaxf(v, 0.0f);
                C[(size_t)m * N + n] = v;
            }
        }
    }
}

// --------------------------------- softmax ---------------------------------
__global__ __launch_bounds__(128) void softmax_kernel()
{
    const int p = blockIdx.x, t = threadIdx.x;
    __shared__ float red[128];
    float v = (t < 81) ? g_cls[p * 81 + t] : -3.0e38f;
    red[t] = v; __syncthreads();
    for (int s = 64; s > 0; s >>= 1) {
        if (t < s) red[t] = fmaxf(red[t], red[t + s]);
        __syncthreads();
    }
    float mx = red[0]; __syncthreads();
    float e = (t < 81) ? expf(v - mx) : 0.0f;
    red[t] = e; __syncthreads();
    for (int s = 64; s > 0; s >>= 1) {
        if (t < s) red[t] += red[t + s];
        __syncthreads();
    }
    float total = red[0];
    if (t < 80) g_scr[p * NCLS + t] = e / total;
}

// ------------------------------- box decode --------------------------------
__global__ __launch_bounds__(256) void decode_kernel(
    const float* __restrict__ props, const int* __restrict__ imidx,
    const float* __restrict__ imsizes)
{
    int idx = blockIdx.x * blockDim.x + threadIdx.x;
    if (idx >= NDET) return;
    int p = idx / NCLS, c = idx - p * NCLS;
    float4 pr = ((const float4*)props)[p];
    float pw = pr.z - pr.x, ph = pr.w - pr.y;
    float pcx = pr.x + 0.5f * pw, pcy = pr.y + 0.5f * ph;
    const float* r = &g_reg[p * 320 + c * 4];
    float dx = r[0] * 0.1f, dy = r[1] * 0.1f;
    float dw = fminf(r[2] * 0.2f, BBOX_CLIP);
    float dh = fminf(r[3] * 0.2f, BBOX_CLIP);
    float ncx = pcx + dx * pw, ncy = pcy + dy * ph;
    float nw = pw * expf(dw), nh = ph * expf(dh);
    int im = imidx[p];
    float hh = imsizes[im * 2 + 0], ww = imsizes[im * 2 + 1];
    float x1 = fminf(fmaxf(ncx - 0.5f * nw, 0.0f), ww);
    float y1 = fminf(fmaxf(ncy - 0.5f * nh, 0.0f), hh);
    float x2 = fminf(fmaxf(ncx + 0.5f * nw, 0.0f), ww);
    float y2 = fminf(fmaxf(ncy + 0.5f * nh, 0.0f), hh);
    float s = g_scr[idx];
    bool valid = (s > 0.05f) && (x2 - x1 > 0.0f) && (y2 - y1 > 0.0f);
    float sm = valid ? s : 0.0f;
    g_boxes[idx] = make_float4(x1, y1, x2, y2);
    // descending sort key: (score, tie -> smaller idx first)
    g_keysA[idx] = ((u64)__float_as_uint(sm) << 32) | (u32)(~(u32)idx);
}

// -------------------------- bitonic sort machinery -------------------------
__device__ __forceinline__ void bitonic2048_desc(u64* s)
{
    const int t = threadIdx.x; // 1024 threads
    for (int k = 2; k <= 2048; k <<= 1) {
        for (int j = k >> 1; j > 0; j >>= 1) {
            __syncthreads();
            int i   = ((t & ~(j - 1)) << 1) | (t & (j - 1));
            int ixj = i | j;
            bool dir = ((i & k) == 0); // descending region
            u64 a = s[i], b = s[ixj];
            if ((a < b) == dir) { s[i] = b; s[ixj] = a; }
        }
    }
    __syncthreads();
}

__global__ __launch_bounds__(1024) void local_sort_kernel(u64* __restrict__ keys)
{
    __shared__ u64 s[2048];
    const int base = blockIdx.x * 2048, t = threadIdx.x;
    s[t] = keys[base + t];
    s[t + 1024] = keys[base + t + 1024];
    bitonic2048_desc(s);
    keys[base + t] = s[t];
    keys[base + t + 1024] = s[t + 1024];
}

// Tournament merge: block a merges sorted-desc chunks (2a, 2a+1) of src,
// keeps the top 2048 sorted desc into dst chunk a. Odd leftover -> copy.
__global__ __launch_bounds__(1024) void merge_kernel(
    const u64* __restrict__ src, u64* __restrict__ dst, int nc)
{
    const int a = blockIdx.x, t = threadIdx.x;
    const int c0 = 2 * a, c1 = c0 + 1;
    if (c1 >= nc) {
        dst[a * 2048 + t]        = src[c0 * 2048 + t];
        dst[a * 2048 + t + 1024] = src[c0 * 2048 + t + 1024];
        return;
    }
    __shared__ u64 s[2048];
    // fused first compare-exchange of the bitonic merge: lower half = top2048
    for (int e = t; e < 2048; e += 1024) {
        u64 x = src[c0 * 2048 + e];
        u64 y = src[c1 * 2048 + 2047 - e];
        s[e] = (x > y) ? x : y;
    }
    for (int j = 1024; j > 0; j >>= 1) {
        __syncthreads();
        int i   = ((t & ~(j - 1)) << 1) | (t & (j - 1));
        int ixj = i | j;
        u64 p = s[i], q = s[ixj];
        if (p < q) { s[i] = q; s[ixj] = p; }
    }
    __syncthreads();
    dst[a * 2048 + t]        = s[t];
    dst[a * 2048 + t + 1024] = s[t + 1024];
}

// ------------------------------ topk gather --------------------------------
__global__ __launch_bounds__(256) void gather_kernel(const int* __restrict__ imidx)
{
    int r = blockIdx.x * blockDim.x + threadIdx.x;
    if (r >= KNMS) return;
    u64 key = g_keysA[r];
    u32 idx = ~((u32)key);
    float s = __uint_as_float((u32)(key >> 32));
    float4 b = g_boxes[idx];
    int p = idx / NCLS, c = idx - p * NCLS;
    int im = imidx[p];
    float off = (float)(im * NCLS + c) * 100000.0f;
    g_ob[r] = make_float4(b.x + off, b.y + off, b.z + off, b.w + off);
    g_bk[r] = b;
    g_sk[r] = s;
    g_ck[r] = c;
    g_imk[r] = im;
    g_vk[r] = (s > 0.0f) ? 1 : 0;
}

// --------------------------------- NMS -------------------------------------
__global__ __launch_bounds__(64) void nms_mask_kernel()
{
    __shared__ float4 cb[64];
    const int t = threadIdx.x;
    const int c0 = blockIdx.x * 64;
    cb[t] = g_ob[c0 + t];
    __syncthreads();
    const int row = blockIdx.y * 64 + t;
    float4 rb = g_ob[row];
    float ra = (rb.z - rb.x) * (rb.w - rb.y);
    u64 bits = 0;
    #pragma unroll 4
    for (int j = 0; j < 64; j++) {
        float4 c = cb[j];
        float lx = fmaxf(rb.x, c.x), ly = fmaxf(rb.y, c.y);
        float rx = fminf(rb.z, c.z), ry = fminf(rb.w, c.w);
        float w = fmaxf(rx - lx, 0.0f), h = fmaxf(ry - ly, 0.0f);
        float inter = w * h;
        float ca = (c.z - c.x) * (c.w - c.y);
        float iou = inter / (ra + ca - inter + 1e-9f);
        if (iou > 0.5f) bits |= (1ULL << j);
    }
    g_mask[(size_t)row * 32 + blockIdx.x] = bits;
}

__global__ __launch_bounds__(32) void nms_scan_kernel()
{
    const int lane = threadIdx.x;
    u64 remv = 0;
    for (int i = 0; i < KNMS; i++) {
        u64 w = __shfl_sync(0xffffffffu, remv, i >> 6);
        bool kept = g_vk[i] && !((w >> (i & 63)) & 1ULL);
        if (kept) remv |= g_mask[(size_t)i * 32 + lane];
        if (lane == 0) g_keep[i] = kept ? 1 : 0;
    }
}

// -------------------------- per-image top-100 ------------------------------
__global__ __launch_bounds__(1024) void topk_image_kernel(float* __restrict__ out)
{
    __shared__ u64 s[2048];
    const int img = blockIdx.x, t = threadIdx.x;
    for (int e = t; e < 2048; e += 1024) {
        float val = (g_imk[e] == img) ? (g_keep[e] ? g_sk[e] : 0.0f) : -1.0f;
        u32 bits = __float_as_uint(val);
        u32 u = (bits & 0x80000000u) ? ~bits : (bits | 0x80000000u);
        s[e] = ((u64)u << 32) | (u32)(2047 - e);
    }
    bitonic2048_desc(s);
    if (t < 100) {
        u64 key = s[t];
        int r = 2047 - (int)(key & 0xFFFFFFFFu);
        u32 u = (u32)(key >> 32);
        float score = (u & 0x80000000u) ? __uint_as_float(u & 0x7FFFFFFFu) : 0.0f;
        float4 b = g_bk[r];
        out[(img * 100 + t) * 4 + 0] = b.x;
        out[(img * 100 + t) * 4 + 1] = b.y;
        out[(img * 100 + t) * 4 + 2] = b.z;
        out[(img * 100 + t) * 4 + 3] = b.w;
        out[1600 + img * 100 + t] = score;
        out[2000 + img * 100 + t] = (float)g_ck[r];
    }
}

// ------------------------------- launcher ----------------------------------
extern "C" void kernel_launch(void* const* d_in, const int* in_sizes, int n_in,
                              void* d_out, int out_size)
{
    const float* proposals = (const float*)d_in[0];
    const int*   imidx     = (const int*)d_in[1];
    const float* f0        = (const float*)d_in[2];
    const float* f1        = (const float*)d_in[3];
    const float* f2        = (const float*)d_in[4];
    const float* f3        = (const float*)d_in[5];
    const float* imsizes   = (const float*)d_in[6];
    const float* fc0_w     = (const float*)d_in[7];
    const float* fc0_b     = (const float*)d_in[8];
    const float* fc1_w     = (const float*)d_in[9];
    const float* fc1_b     = (const float*)d_in[10];
    const float* cls_w     = (const float*)d_in[11];
    const float* cls_b     = (const float*)d_in[12];
    const float* reg_w     = (const float*)d_in[13];
    const float* reg_b     = (const float*)d_in[14];
    float* out = (float*)d_out;

    void *px, *ph1, *ph2, *pcls, *preg, *pkA, *pkB;
    cudaGetSymbolAddress(&px,  g_x);
    cudaGetSymbolAddress(&ph1, g_h1);
    cudaGetSymbolAddress(&ph2, g_h2);
    cudaGetSymbolAddress(&pcls, g_cls);
    cudaGetSymbolAddress(&preg, g_reg);
    cudaGetSymbolAddress(&pkA, g_keysA);
    cudaGetSymbolAddress(&pkB, g_keysB);

    roi_align_kernel<<<P_PROP * 7, 256>>>(proposals, imidx, f0, f1, f2, f3);

    gemm_kernel<<<dim3(16, 16), 256>>>((const float*)px,  fc0_w, fc0_b, (float*)ph1, 1024, FEAT, 1);
    gemm_kernel<<<dim3(16, 16), 256>>>((const float*)ph1, fc1_w, fc1_b, (float*)ph2, 1024, CLIN, 1);
    gemm_kernel<<<dim3(2, 16),  256>>>((const float*)ph2, cls_w, cls_b, (float*)pcls,   81, CLIN, 0);
    gemm_kernel<<<dim3(5, 16),  256>>>((const float*)ph2, reg_w, reg_b, (float*)preg,  320, CLIN, 0);

    softmax_kernel<<<P_PROP, 128>>>();
    decode_kernel<<<NDET / 256, 256>>>(proposals, imidx, imsizes);

    // exact top-2048: local sorts + tournament merges (ping-pong A<->B)
    local_sort_kernel<<<40, 1024>>>((u64*)pkA);
    {
        int nc = 40;
        bool srcA = true;
        while (nc > 1) {
            int nd = (nc + 1) / 2;
            merge_kernel<<<nd, 1024>>>(srcA ? (const u64*)pkA : (const u64*)pkB,
                                       srcA ? (u64*)pkB : (u64*)pkA, nc);
            nc = nd;
            srcA = !srcA;
        }
        // 40->20->10->5->3->2->1 : 6 merges, final result lands in g_keysA
    }

    gather_kernel<<<KNMS / 256, 256>>>(imidx);
    nms_mask_kernel<<<dim3(32, 32), 64>>>();
    nms_scan_kernel<<<1, 32>>>();
    topk_image_kernel<<<4, 1024>>>(out);
}